// round 2
// baseline (speedup 1.0000x reference)
#include <cuda_runtime.h>
#include <mma.h>

using namespace nvcuda;

static constexpr int T_TOK = 8192;
static constexpr int H_DIM = 2048;
static constexpr int E_NUM = 8;
static constexpr int I_DIM = 1024;
static constexpr int NPAIR = T_TOK * 2;   // top-2: every token contributes exactly 2 pairs

// ---------------- scratch (static device globals; no allocations) ----------------
__device__ float g_gbuf[(long long)NPAIR * I_DIM];   // gate proj, then y = silu(g)*u in-place
__device__ float g_ubuf[(long long)NPAIR * I_DIM];   // up proj
__device__ float g_zbuf[(long long)NPAIR * H_DIM];   // down proj per pair
__device__ int   g_topidx[NPAIR];
__device__ float g_topw[NPAIR];
__device__ int   g_pairloc[NPAIR];                   // (t,k) -> global bucket row
__device__ int   g_bucket[NPAIR];                    // bucket row -> token id
__device__ int   g_counts[E_NUM];
__device__ int   g_offsets[E_NUM + 1];
__device__ int   g_cursors[E_NUM];

// ---------------- tiny setup kernels ----------------
__global__ void init_kernel() {
    int i = threadIdx.x;
    if (i < E_NUM) { g_counts[i] = 0; g_cursors[i] = 0; }
}

// One warp per token: logits = x[t] . w_gate[e], top-2, renormalized weights.
// softmax-then-top2-renorm == softmax over the top-2 logits.
__global__ void router_kernel(const float* __restrict__ x,
                              const float* __restrict__ wg) {
    int warp = threadIdx.x >> 5, lane = threadIdx.x & 31;
    int t = blockIdx.x * 8 + warp;
    if (t >= T_TOK) return;
    float acc[E_NUM];
#pragma unroll
    for (int e = 0; e < E_NUM; e++) acc[e] = 0.f;
    const float4* xr = (const float4*)(x + (size_t)t * H_DIM);
    for (int h4 = lane; h4 < H_DIM / 4; h4 += 32) {
        float4 xv = xr[h4];
#pragma unroll
        for (int e = 0; e < E_NUM; e++) {
            float4 wv = ((const float4*)(wg + (size_t)e * H_DIM))[h4];
            acc[e] += xv.x * wv.x + xv.y * wv.y + xv.z * wv.z + xv.w * wv.w;
        }
    }
#pragma unroll
    for (int e = 0; e < E_NUM; e++)
#pragma unroll
        for (int off = 16; off; off >>= 1)
            acc[e] += __shfl_xor_sync(0xffffffffu, acc[e], off);
    if (lane == 0) {
        int i0 = 0;
        for (int e = 1; e < E_NUM; e++) if (acc[e] > acc[i0]) i0 = e;   // strict > : earliest index wins ties
        int i1 = (i0 == 0) ? 1 : 0;
        for (int e = 0; e < E_NUM; e++) if (e != i0 && acc[e] > acc[i1]) i1 = e;
        float w0 = 1.f / (1.f + expf(acc[i1] - acc[i0]));   // exp arg <= 0
        g_topidx[2 * t] = i0; g_topidx[2 * t + 1] = i1;
        g_topw[2 * t] = w0;   g_topw[2 * t + 1] = 1.f - w0;
        atomicAdd(&g_counts[i0], 1);
        atomicAdd(&g_counts[i1], 1);
    }
}

__global__ void scan_kernel() {
    if (threadIdx.x == 0) {
        int s = 0;
        for (int e = 0; e < E_NUM; e++) { g_offsets[e] = s; s += g_counts[e]; }
        g_offsets[E_NUM] = s;   // == NPAIR always
    }
}

__global__ void scatter_kernel() {
    int t = blockIdx.x * blockDim.x + threadIdx.x;
    if (t >= T_TOK) return;
#pragma unroll
    for (int k = 0; k < 2; k++) {
        int e = g_topidx[2 * t + k];
        int pos = atomicAdd(&g_cursors[e], 1);
        int glob = g_offsets[e] + pos;
        g_bucket[glob] = t;
        g_pairloc[2 * t + k] = glob;
    }
}

// ---------------- grouped GEMM: C[rows in expert bucket] = gather(A) @ W[e]^T ----------------
// mode 0: A=x (gathered by bucket), W=w1, C=g_gbuf, N=I, K=H
// mode 1: A=x (gathered by bucket), W=w3, C=g_ubuf, N=I, K=H
// mode 2: A=g_gbuf (identity rows), W=w2, C=g_zbuf, N=H, K=I
static constexpr int BM = 128, BN = 128, BK = 16;
static constexpr int SAS = BK + 4;   // smem stride 20 floats (mult of 4, conflict padding)

__global__ __launch_bounds__(256, 2)
void gemm_tf32_kernel(int mode,
                      const float* __restrict__ x,
                      const float* __restrict__ Wall,
                      int N, int K, int lda)
{
    const float* A; float* C; const int* list;
    if (mode == 0)      { A = x;      C = g_gbuf; list = g_bucket; }
    else if (mode == 1) { A = x;      C = g_ubuf; list = g_bucket; }
    else                { A = g_gbuf; C = g_zbuf; list = nullptr;  }

    int e    = blockIdx.z;
    int row0 = g_offsets[e];
    int cnt  = g_offsets[e + 1] - row0;
    int m0   = blockIdx.y * BM;
    if (m0 >= cnt) return;
    int n0 = blockIdx.x * BN;

    const float* Wp = Wall + (size_t)e * N * K;

    __shared__ float As[BM][SAS];
    __shared__ float Ws[BN][SAS];

    int tid  = threadIdx.x;
    int warp = tid >> 5, lane = tid & 31;
    int wm = warp & 1, wn = warp >> 1;            // 2 (M) x 4 (N) warps
    int mbase = wm * 64, nbase = wn * 32;

    wmma::fragment<wmma::accumulator, 16, 16, 8, float> acc[4][2];
#pragma unroll
    for (int i = 0; i < 4; i++)
#pragma unroll
        for (int j = 0; j < 2; j++) wmma::fill_fragment(acc[i][j], 0.f);

    // each thread loads 2 float4 per tile (128 rows x 16 cols = 512 float4, 256 threads)
    int r0 = tid >> 2;            // 0..63
    int r1 = r0 + 64;             // 64..127
    int c0 = (tid & 3) * 4;       // 0,4,8,12

    int lr0 = m0 + r0; if (lr0 >= cnt) lr0 = cnt - 1;
    int lr1 = m0 + r1; if (lr1 >= cnt) lr1 = cnt - 1;
    long long arow0 = (long long)(list ? list[row0 + lr0] : (row0 + lr0)) * lda;
    long long arow1 = (long long)(list ? list[row0 + lr1] : (row0 + lr1)) * lda;
    const float* wrow0 = Wp + (size_t)(n0 + r0) * K;
    const float* wrow1 = Wp + (size_t)(n0 + r1) * K;

    for (int k0 = 0; k0 < K; k0 += BK) {
        *(float4*)&As[r0][c0] = *(const float4*)(A + arow0 + k0 + c0);
        *(float4*)&As[r1][c0] = *(const float4*)(A + arow1 + k0 + c0);
        *(float4*)&Ws[r0][c0] = *(const float4*)(wrow0 + k0 + c0);
        *(float4*)&Ws[r1][c0] = *(const float4*)(wrow1 + k0 + c0);
        __syncthreads();
#pragma unroll
        for (int ks = 0; ks < BK; ks += 8) {
            wmma::fragment<wmma::matrix_a, 16, 16, 8, wmma::precision::tf32, wmma::row_major> af[4];
            wmma::fragment<wmma::matrix_b, 16, 16, 8, wmma::precision::tf32, wmma::col_major> bf[2];
#pragma unroll
            for (int i = 0; i < 4; i++) {
                wmma::load_matrix_sync(af[i], &As[mbase + i * 16][ks], SAS);
#pragma unroll
                for (int q = 0; q < af[i].num_elements; q++)
                    af[i].x[q] = wmma::__float_to_tf32(af[i].x[q]);
            }
#pragma unroll
            for (int j = 0; j < 2; j++) {
                wmma::load_matrix_sync(bf[j], &Ws[nbase + j * 16][ks], SAS);
#pragma unroll
                for (int q = 0; q < bf[j].num_elements; q++)
                    bf[j].x[q] = wmma::__float_to_tf32(bf[j].x[q]);
            }
#pragma unroll
            for (int i = 0; i < 4; i++)
#pragma unroll
                for (int j = 0; j < 2; j++)
                    wmma::mma_sync(acc[i][j], af[i], bf[j], acc[i][j]);
        }
        __syncthreads();
    }

    // store (stage partial M-tiles through smem; As is free after the trailing barrier)
    float* stage = &As[0][0] + warp * 256;   // 16x16 per-warp staging
#pragma unroll
    for (int i = 0; i < 4; i++) {
        int mlo = mbase + i * 16;
        if (m0 + mlo >= cnt) continue;
#pragma unroll
        for (int j = 0; j < 2; j++) {
            int nlo = n0 + nbase + j * 16;
            float* cp = C + (size_t)(row0 + m0 + mlo) * N + nlo;
            if (m0 + mlo + 16 <= cnt) {
                wmma::store_matrix_sync(cp, acc[i][j], N, wmma::mem_row_major);
            } else {
                wmma::store_matrix_sync(stage, acc[i][j], 16, wmma::mem_row_major);
                __syncwarp();
                int valid = cnt - (m0 + mlo);
                for (int q = lane; q < valid * 16; q += 32)
                    cp[(size_t)(q / 16) * N + (q % 16)] = stage[q];
                __syncwarp();
            }
        }
    }
}

// ---------------- elementwise SwiGLU: y = silu(g) * u, in-place into g_gbuf ----------------
__global__ void act_kernel() {
    long long i = (long long)blockIdx.x * blockDim.x + threadIdx.x;  // NPAIR*I_DIM/4 threads
    float4 g = ((const float4*)g_gbuf)[i];
    float4 u = ((const float4*)g_ubuf)[i];
    float4 y;
    y.x = g.x / (1.f + expf(-g.x)) * u.x;
    y.y = g.y / (1.f + expf(-g.y)) * u.y;
    y.z = g.z / (1.f + expf(-g.z)) * u.z;
    y.w = g.w / (1.f + expf(-g.w)) * u.w;
    ((float4*)g_gbuf)[i] = y;
}

// ---------------- combine: out[t] = w0*z[loc0] + w1*z[loc1] (deterministic gather) --------
__global__ void combine_kernel(float* __restrict__ out) {
    int idx = blockIdx.x * blockDim.x + threadIdx.x;   // T_TOK*H_DIM/4 threads
    int t = idx >> 9;            // H_DIM/4 = 512
    int c = idx & 511;
    int l0 = g_pairloc[2 * t], l1 = g_pairloc[2 * t + 1];
    float w0 = g_topw[2 * t], w1 = g_topw[2 * t + 1];
    const float4* z = (const float4*)g_zbuf;
    float4 a = z[(size_t)l0 * (H_DIM / 4) + c];
    float4 b = z[(size_t)l1 * (H_DIM / 4) + c];
    float4 o;
    o.x = w0 * a.x + w1 * b.x;
    o.y = w0 * a.y + w1 * b.y;
    o.z = w0 * a.z + w1 * b.z;
    o.w = w0 * a.w + w1 * b.w;
    ((float4*)out)[idx] = o;
}

// ---------------- launch ----------------
extern "C" void kernel_launch(void* const* d_in, const int* in_sizes, int n_in,
                              void* d_out, int out_size) {
    const float* x  = (const float*)d_in[0];   // [T, H]
    const float* wg = (const float*)d_in[1];   // [E, H]
    const float* w1 = (const float*)d_in[2];   // [E, I, H]
    const float* w3 = (const float*)d_in[3];   // [E, I, H]
    const float* w2 = (const float*)d_in[4];   // [E, H, I]
    float* out = (float*)d_out;                // [T, H]

    init_kernel<<<1, 32>>>();
    router_kernel<<<T_TOK / 8, 256>>>(x, wg);
    scan_kernel<<<1, 32>>>();
    scatter_kernel<<<T_TOK / 256, 256>>>();

    dim3 g1(I_DIM / BN, T_TOK / BM, E_NUM);
    gemm_tf32_kernel<<<g1, 256>>>(0, x, w1, I_DIM, H_DIM, H_DIM);
    gemm_tf32_kernel<<<g1, 256>>>(1, x, w3, I_DIM, H_DIM, H_DIM);

    act_kernel<<<(NPAIR * I_DIM / 4) / 256, 256>>>();

    dim3 g2(H_DIM / BN, T_TOK / BM, E_NUM);
    gemm_tf32_kernel<<<g2, 256>>>(2, nullptr, w2, H_DIM, I_DIM, I_DIM);

    combine_kernel<<<(T_TOK * H_DIM / 4) / 256, 256>>>(out);
}